// round 1
// baseline (speedup 1.0000x reference)
#include <cuda_runtime.h>
#include <math.h>

#define NMAX  100000
#define EMAX  1600000
#define FIN   512
#define H1    8
#define D1    64      // H1 * C1
#define NCLS  40
#define SLOPE 0.2f

// ---------------- scratch (static device globals; no allocations) ----------
__device__ int g_is64;
__device__ __align__(256) int   g_src[EMAX];
__device__ __align__(256) int   g_dst[EMAX];
__device__ __align__(256) float g_h1  [NMAX * D1];
__device__ __align__(256) float g_as1 [NMAX * H1];
__device__ __align__(256) float g_ad1 [NMAX * H1];
__device__ __align__(256) int   g_max1[NMAX * H1];
__device__ __align__(256) float g_den1[NMAX * H1];
__device__ __align__(256) float g_acc1[NMAX * D1];
__device__ __align__(256) float g_hact[NMAX * D1];
__device__ __align__(256) float g_h2  [NMAX * NCLS];
__device__ __align__(256) float g_as2 [NMAX];
__device__ __align__(256) float g_ad2 [NMAX];
__device__ __align__(256) int   g_max2[NMAX];
__device__ __align__(256) float g_den2[NMAX];
__device__ __align__(256) float g_acc2[NMAX * NCLS];

// ---------------- helpers ---------------------------------------------------
__device__ __forceinline__ int f2o(float f) {         // float -> order-preserving int
    int i = __float_as_int(f);
    return i >= 0 ? i : i ^ 0x7FFFFFFF;
}
__device__ __forceinline__ float o2f(int i) {         // inverse
    return __int_as_float(i >= 0 ? i : i ^ 0x7FFFFFFF);
}
__device__ __forceinline__ float lrelu(float v) { return v > 0.f ? v : SLOPE * v; }

// ---------------- edge index normalization ---------------------------------
__global__ void k_detect(const int* __restrict__ ei) {
    if (threadIdx.x == 0 && blockIdx.x == 0) {
        int nz = 0;
        // int64 little-endian: odd int32 positions are high words == 0 (values < 2^31)
        for (int i = 1; i < 64; i += 2) nz |= ei[i];
        g_is64 = (nz == 0) ? 1 : 0;
    }
}

__global__ void k_convert(const void* __restrict__ ei, int E) {
    int i = blockIdx.x * blockDim.x + threadIdx.x;
    if (i >= E) return;
    if (g_is64) {
        const long long* p = (const long long*)ei;
        g_src[i] = (int)p[i];
        g_dst[i] = (int)p[(long long)E + i];
    } else {
        const int* p = (const int*)ei;
        g_src[i] = p[i];
        g_dst[i] = p[E + i];
    }
}

// ---------------- GEMM1: h1[N,64] = x[N,512] @ W1[512,64] -------------------
__global__ void k_gemm1(const float* __restrict__ x, const float* __restrict__ W, int n) {
    __shared__ float As[32][65];   // As[k][r]
    __shared__ float Bs[32][64];   // Bs[k][c]
    const int row0 = blockIdx.x * 64;
    const int t  = threadIdx.x;
    const int tx = t & 15, ty = t >> 4;

    float acc[4][4];
#pragma unroll
    for (int i = 0; i < 4; i++)
#pragma unroll
        for (int j = 0; j < 4; j++) acc[i][j] = 0.f;

    for (int k0 = 0; k0 < FIN; k0 += 32) {
#pragma unroll
        for (int i = 0; i < 8; i++) {
            int idx = t + i * 256;            // 2048 A elems
            int r = idx >> 5, k = idx & 31;
            int row = row0 + r;
            As[k][r] = (row < n) ? x[row * FIN + k0 + k] : 0.f;
        }
#pragma unroll
        for (int i = 0; i < 8; i++) {
            int idx = t + i * 256;            // 2048 B elems
            int k = idx >> 6, c = idx & 63;
            Bs[k][c] = W[(k0 + k) * D1 + c];
        }
        __syncthreads();
#pragma unroll
        for (int kk = 0; kk < 32; kk++) {
            float a[4], b[4];
#pragma unroll
            for (int i = 0; i < 4; i++) a[i] = As[kk][ty * 4 + i];
#pragma unroll
            for (int j = 0; j < 4; j++) b[j] = Bs[kk][tx * 4 + j];
#pragma unroll
            for (int i = 0; i < 4; i++)
#pragma unroll
                for (int j = 0; j < 4; j++) acc[i][j] += a[i] * b[j];
        }
        __syncthreads();
    }
#pragma unroll
    for (int i = 0; i < 4; i++) {
        int row = row0 + ty * 4 + i;
        if (row < n)
#pragma unroll
            for (int j = 0; j < 4; j++)
                g_h1[row * D1 + tx * 4 + j] = acc[i][j];
    }
}

// ---------------- layer-1 node prep -----------------------------------------
__global__ void k_node1a(const float* __restrict__ att_s, const float* __restrict__ att_d, int n) {
    int gid = blockIdx.x * blockDim.x + threadIdx.x;
    if (gid >= n * H1) return;
    int node = gid >> 3, h = gid & 7;
    int base = node * D1 + h * 8;
    float a_s = 0.f, a_d = 0.f;
#pragma unroll
    for (int c = 0; c < 8; c++) {
        float hv = g_h1[base + c];
        a_s += hv * att_s[h * 8 + c];
        a_d += hv * att_d[h * 8 + c];
        g_acc1[base + c] = 0.f;
    }
    g_as1[gid] = a_s;
    g_ad1[gid] = a_d;
    g_max1[gid] = f2o(lrelu(a_s + a_d));   // self-loop seeds the segment max
    g_den1[gid] = 0.f;
}

// ---------------- layer-1 edge max ------------------------------------------
__global__ void k_emax1(int E) {
    int e = blockIdx.x * blockDim.x + threadIdx.x;
    if (e >= E) return;
    int s = g_src[e], d = g_dst[e];
    const float4* as = (const float4*)(g_as1 + s * 8);
    const float4* ad = (const float4*)(g_ad1 + d * 8);
    float4 s0 = as[0], s1 = as[1], d0 = ad[0], d1 = ad[1];
    int* mx = g_max1 + d * 8;
    atomicMax(mx + 0, f2o(lrelu(s0.x + d0.x)));
    atomicMax(mx + 1, f2o(lrelu(s0.y + d0.y)));
    atomicMax(mx + 2, f2o(lrelu(s0.z + d0.z)));
    atomicMax(mx + 3, f2o(lrelu(s0.w + d0.w)));
    atomicMax(mx + 4, f2o(lrelu(s1.x + d1.x)));
    atomicMax(mx + 5, f2o(lrelu(s1.y + d1.y)));
    atomicMax(mx + 6, f2o(lrelu(s1.z + d1.z)));
    atomicMax(mx + 7, f2o(lrelu(s1.w + d1.w)));
}

// ---------------- layer-1 fused exp + denom + aggregate ----------------------
__global__ void k_eagg1(int E) {
    int gid = blockIdx.x * blockDim.x + threadIdx.x;
    if (gid >= E * 16) return;
    int e = gid >> 4, c4 = gid & 15;            // 16 float4 chunks of 64 ch
    int s = g_src[e], d = g_dst[e];
    int h = c4 >> 1;                             // head = 8ch = 2 chunks
    float eh = lrelu(g_as1[s * 8 + h] + g_ad1[d * 8 + h]);
    float w = expf(eh - o2f(g_max1[d * 8 + h]));
    if ((c4 & 1) == 0) atomicAdd(&g_den1[d * 8 + h], w);
    float4 hv = ((const float4*)g_h1)[s * 16 + c4];
    float4 v = make_float4(hv.x * w, hv.y * w, hv.z * w, hv.w * w);
    atomicAdd((float4*)(g_acc1 + d * 64 + c4 * 4), v);
}

// ---------------- layer-1 node epilogue: alpha divide + bias + ELU ----------
__global__ void k_node1b(const float* __restrict__ b1, int n) {
    int gid = blockIdx.x * blockDim.x + threadIdx.x;
    if (gid >= n * H1) return;
    int node = gid >> 3, h = gid & 7;
    float mx = o2f(g_max1[gid]);
    float es = lrelu(g_as1[gid] + g_ad1[gid]);
    float eself = expf(es - mx);
    float inv = 1.f / (g_den1[gid] + eself + 1e-16f);
    int base = node * D1 + h * 8;
#pragma unroll
    for (int c = 0; c < 8; c++) {
        float v = (g_acc1[base + c] + g_h1[base + c] * eself) * inv + b1[h * 8 + c];
        g_hact[base + c] = v > 0.f ? v : expm1f(v);   // ELU
    }
}

// ---------------- GEMM2: h2[N,40] = hact[N,64] @ W2[64,40] -------------------
__global__ void k_gemm2(const float* __restrict__ W2, int n) {
    __shared__ float Hs[64][65];
    __shared__ float Ws[64][NCLS];
    const int row0 = blockIdx.x * 64;
    const int t = threadIdx.x;

    for (int i = t; i < 64 * NCLS; i += 256) Ws[i / NCLS][i % NCLS] = W2[i];
#pragma unroll
    for (int i = 0; i < 16; i++) {
        int idx = t + i * 256;
        int r = idx >> 6, k = idx & 63;
        int row = row0 + r;
        Hs[r][k] = (row < n) ? g_hact[row * D1 + k] : 0.f;
    }
    __syncthreads();

    int r  = t >> 2;               // 0..63
    int c0 = (t & 3) * 10;         // 0,10,20,30
    float acc[10];
#pragma unroll
    for (int j = 0; j < 10; j++) acc[j] = 0.f;
#pragma unroll
    for (int k = 0; k < 64; k++) {
        float hv = Hs[r][k];
#pragma unroll
        for (int j = 0; j < 10; j++) acc[j] += hv * Ws[k][c0 + j];
    }
    int row = row0 + r;
    if (row < n)
#pragma unroll
        for (int j = 0; j < 10; j++) g_h2[row * NCLS + c0 + j] = acc[j];
}

// ---------------- layer-2 node prep ------------------------------------------
__global__ void k_node2a(const float* __restrict__ att_s, const float* __restrict__ att_d, int n) {
    int node = blockIdx.x * blockDim.x + threadIdx.x;
    if (node >= n) return;
    float a_s = 0.f, a_d = 0.f;
#pragma unroll
    for (int c = 0; c < NCLS; c++) {
        float hv = g_h2[node * NCLS + c];
        a_s += hv * att_s[c];
        a_d += hv * att_d[c];
        g_acc2[node * NCLS + c] = 0.f;
    }
    g_as2[node] = a_s;
    g_ad2[node] = a_d;
    g_max2[node] = f2o(lrelu(a_s + a_d));
    g_den2[node] = 0.f;
}

// ---------------- layer-2 edge max ------------------------------------------
__global__ void k_emax2(int E) {
    int e = blockIdx.x * blockDim.x + threadIdx.x;
    if (e >= E) return;
    int s = g_src[e], d = g_dst[e];
    atomicMax(&g_max2[d], f2o(lrelu(g_as2[s] + g_ad2[d])));
}

// ---------------- layer-2 fused exp + denom + aggregate ----------------------
__global__ void k_eagg2(int E) {
    int gid = blockIdx.x * blockDim.x + threadIdx.x;
    if (gid >= E * 10) return;
    int e = gid / 10, c4 = gid - e * 10;        // 10 float4 chunks of 40 ch
    int s = g_src[e], d = g_dst[e];
    float eh = lrelu(g_as2[s] + g_ad2[d]);
    float w = expf(eh - o2f(g_max2[d]));
    if (c4 == 0) atomicAdd(&g_den2[d], w);
    float4 hv = ((const float4*)g_h2)[s * 10 + c4];
    float4 v = make_float4(hv.x * w, hv.y * w, hv.z * w, hv.w * w);
    atomicAdd((float4*)(g_acc2 + d * NCLS + c4 * 4), v);
}

// ---------------- layer-2 node epilogue + row softmax ------------------------
__global__ void k_node2b(const float* __restrict__ b2, float* __restrict__ out, int n) {
    int node = blockIdx.x * blockDim.x + threadIdx.x;
    if (node >= n) return;
    float mx = o2f(g_max2[node]);
    float es = lrelu(g_as2[node] + g_ad2[node]);
    float eself = expf(es - mx);
    float inv = 1.f / (g_den2[node] + eself + 1e-16f);

    float v[NCLS];
    float m = -INFINITY;
#pragma unroll
    for (int c = 0; c < NCLS; c++) {
        float t = (g_acc2[node * NCLS + c] + g_h2[node * NCLS + c] * eself) * inv + b2[c];
        v[c] = t;
        m = fmaxf(m, t);
    }
    float ssum = 0.f;
#pragma unroll
    for (int c = 0; c < NCLS; c++) {
        v[c] = expf(v[c] - m);
        ssum += v[c];
    }
    float r = 1.f / ssum;
#pragma unroll
    for (int c = 0; c < NCLS; c++) out[node * NCLS + c] = v[c] * r;
}

// ---------------- launch ------------------------------------------------------
extern "C" void kernel_launch(void* const* d_in, const int* in_sizes, int n_in,
                              void* d_out, int out_size) {
    const float* x   = (const float*)d_in[0];
    const void*  ei  = d_in[1];
    const float* W1  = (const float*)d_in[2];
    const float* as1 = (const float*)d_in[3];
    const float* ad1 = (const float*)d_in[4];
    const float* b1  = (const float*)d_in[5];
    const float* W2  = (const float*)d_in[6];
    const float* as2 = (const float*)d_in[7];
    const float* ad2 = (const float*)d_in[8];
    const float* b2  = (const float*)d_in[9];
    float* out = (float*)d_out;

    int n = in_sizes[0] / FIN;       // 100000
    int E = in_sizes[1] / 2;         // 1600000

    k_detect <<<1, 32>>>((const int*)ei);
    k_convert<<<(E + 255) / 256, 256>>>(ei, E);

    // layer 1
    k_gemm1  <<<(n + 63) / 64, 256>>>(x, W1, n);
    k_node1a <<<(n * H1 + 255) / 256, 256>>>(as1, ad1, n);
    k_emax1  <<<(E + 255) / 256, 256>>>(E);
    k_eagg1  <<<(E * 16 + 255) / 256, 256>>>(E);
    k_node1b <<<(n * H1 + 255) / 256, 256>>>(b1, n);

    // layer 2
    k_gemm2  <<<(n + 63) / 64, 256>>>(W2, n);
    k_node2a <<<(n + 255) / 256, 256>>>(as2, ad2, n);
    k_emax2  <<<(E + 255) / 256, 256>>>(E);
    k_eagg2  <<<(E * 10 + 255) / 256, 256>>>(E);
    k_node2b <<<(n + 255) / 256, 256>>>(b2, out, n);
}

// round 2
// speedup vs baseline: 1.0779x; 1.0779x over previous
#include <cuda_runtime.h>
#include <math.h>

#define NMAX  100000
#define EMAX  1600000
#define FIN   512
#define H1    8
#define D1    64      // H1 * C1
#define NCLS  40
#define SLOPE 0.2f
#define SCAN_B 1024

// ---------------- scratch (static device globals; no allocations) ----------
__device__ int g_is64;
__device__ __align__(256) int   g_src [EMAX];
__device__ __align__(256) int   g_dst [EMAX];
__device__ __align__(256) int   g_csr [EMAX];      // src ids grouped by dst
__device__ __align__(256) int   g_deg [NMAX];
__device__ __align__(256) int   g_row [NMAX + 1];  // CSR row pointers
__device__ __align__(256) int   g_cur [NMAX];
__device__ __align__(256) int   g_bsum[SCAN_B];
__device__ __align__(256) float g_h1  [NMAX * D1];
__device__ __align__(256) float g_as1 [NMAX * H1];
__device__ __align__(256) float g_ad1 [NMAX * H1];
__device__ __align__(256) float g_hact[NMAX * D1];
__device__ __align__(256) float g_h2  [NMAX * NCLS];
__device__ __align__(256) float g_as2 [NMAX];
__device__ __align__(256) float g_ad2 [NMAX];

__device__ __forceinline__ float lrelu(float v) { return v > 0.f ? v : SLOPE * v; }

// ---------------- edge index normalization + degree histogram ---------------
__global__ void k_detect(const int* __restrict__ ei) {
    if (threadIdx.x == 0 && blockIdx.x == 0) {
        int nz = 0;
        for (int i = 1; i < 64; i += 2) nz |= ei[i];   // int64 high words all zero?
        g_is64 = (nz == 0) ? 1 : 0;
    }
}

__global__ void k_zero(int n) {
    int i = blockIdx.x * blockDim.x + threadIdx.x;
    if (i < n) g_deg[i] = 0;
}

__global__ void k_build(const void* __restrict__ ei, int E) {
    int i = blockIdx.x * blockDim.x + threadIdx.x;
    if (i >= E) return;
    int s, d;
    if (g_is64) {
        const long long* p = (const long long*)ei;
        s = (int)p[i];
        d = (int)p[(long long)E + i];
    } else {
        const int* p = (const int*)ei;
        s = p[i];
        d = p[E + i];
    }
    g_src[i] = s;
    g_dst[i] = d;
    atomicAdd(&g_deg[d], 1);
}

// ---------------- exclusive scan of g_deg -> g_row --------------------------
__global__ void k_scan1(int n) {
    __shared__ int sh[SCAN_B];
    int tid = threadIdx.x;
    int i = blockIdx.x * SCAN_B + tid;
    int v = (i < n) ? g_deg[i] : 0;
    sh[tid] = v;
    __syncthreads();
#pragma unroll
    for (int off = 1; off < SCAN_B; off <<= 1) {
        int t = (tid >= off) ? sh[tid - off] : 0;
        __syncthreads();
        sh[tid] += t;
        __syncthreads();
    }
    if (i < n) g_row[i] = sh[tid] - v;          // local exclusive
    if (tid == SCAN_B - 1) g_bsum[blockIdx.x] = sh[tid];
}

__global__ void k_scan2(int nb) {
    __shared__ int sh[SCAN_B];
    int tid = threadIdx.x;
    int v = (tid < nb) ? g_bsum[tid] : 0;
    sh[tid] = v;
    __syncthreads();
#pragma unroll
    for (int off = 1; off < SCAN_B; off <<= 1) {
        int t = (tid >= off) ? sh[tid - off] : 0;
        __syncthreads();
        sh[tid] += t;
        __syncthreads();
    }
    g_bsum[tid] = sh[tid] - v;                  // exclusive block offsets
}

__global__ void k_scan3(int n, int E) {
    int i = blockIdx.x * blockDim.x + threadIdx.x;
    if (i < n) {
        int r = g_row[i] + g_bsum[i >> 10];
        g_row[i] = r;
        g_cur[i] = r;
    } else if (i == n) {
        g_row[n] = E;
    }
}

__global__ void k_scatter(int E) {
    int i = blockIdx.x * blockDim.x + threadIdx.x;
    if (i >= E) return;
    int d = g_dst[i];
    int pos = atomicAdd(&g_cur[d], 1);
    g_csr[pos] = g_src[i];
}

// ---------------- GEMM1: h1[N,64] = x[N,512] @ W1[512,64] -------------------
__global__ void k_gemm1(const float* __restrict__ x, const float* __restrict__ W, int n) {
    __shared__ float As[32][65];
    __shared__ float Bs[32][64];
    const int row0 = blockIdx.x * 64;
    const int t  = threadIdx.x;
    const int tx = t & 15, ty = t >> 4;

    float acc[4][4];
#pragma unroll
    for (int i = 0; i < 4; i++)
#pragma unroll
        for (int j = 0; j < 4; j++) acc[i][j] = 0.f;

    for (int k0 = 0; k0 < FIN; k0 += 32) {
#pragma unroll
        for (int i = 0; i < 8; i++) {
            int idx = t + i * 256;
            int r = idx >> 5, k = idx & 31;
            int row = row0 + r;
            As[k][r] = (row < n) ? x[row * FIN + k0 + k] : 0.f;
        }
#pragma unroll
        for (int i = 0; i < 8; i++) {
            int idx = t + i * 256;
            int k = idx >> 6, c = idx & 63;
            Bs[k][c] = W[(k0 + k) * D1 + c];
        }
        __syncthreads();
#pragma unroll
        for (int kk = 0; kk < 32; kk++) {
            float a[4], b[4];
#pragma unroll
            for (int i = 0; i < 4; i++) a[i] = As[kk][ty * 4 + i];
#pragma unroll
            for (int j = 0; j < 4; j++) b[j] = Bs[kk][tx * 4 + j];
#pragma unroll
            for (int i = 0; i < 4; i++)
#pragma unroll
                for (int j = 0; j < 4; j++) acc[i][j] += a[i] * b[j];
        }
        __syncthreads();
    }
#pragma unroll
    for (int i = 0; i < 4; i++) {
        int row = row0 + ty * 4 + i;
        if (row < n)
#pragma unroll
            for (int j = 0; j < 4; j++)
                g_h1[row * D1 + tx * 4 + j] = acc[i][j];
    }
}

// ---------------- layer-1 attention logits -----------------------------------
__global__ void k_node1a(const float* __restrict__ att_s, const float* __restrict__ att_d, int n) {
    int gid = blockIdx.x * blockDim.x + threadIdx.x;
    if (gid >= n * H1) return;
    int node = gid >> 3, h = gid & 7;
    int base = node * D1 + h * 8;
    float a_s = 0.f, a_d = 0.f;
#pragma unroll
    for (int c = 0; c < 8; c++) {
        float hv = g_h1[base + c];
        a_s += hv * att_s[h * 8 + c];
        a_d += hv * att_d[h * 8 + c];
    }
    g_as1[gid] = a_s;
    g_ad1[gid] = a_d;
}

// ---------------- layer-1 fused aggregate + epilogue (warp per dst) ---------
__global__ void k_agg1(const float* __restrict__ b1, int n) {
    int warp = (blockIdx.x * blockDim.x + threadIdx.x) >> 5;
    int lane = threadIdx.x & 31;
    if (warp >= n) return;
    int d = warp;
    int h = lane >> 2;                   // lane owns channels 2*lane, 2*lane+1 (head = lane/4)
    float adv = g_ad1[d * 8 + h];

    float2 acc = make_float2(0.f, 0.f);
    float den = 0.f;

    int s0 = g_row[d], s1 = g_row[d + 1];
#pragma unroll 4
    for (int j = s0; j < s1; j++) {
        int s = g_csr[j];                // broadcast load
        float a = g_as1[s * 8 + h];
        float w = expf(lrelu(a + adv));
        float2 hv = ((const float2*)g_h1)[s * 32 + lane];
        acc.x += w * hv.x;
        acc.y += w * hv.y;
        den += w;
    }
    // self loop
    {
        float w = expf(lrelu(g_as1[d * 8 + h] + adv));
        float2 hv = ((const float2*)g_h1)[d * 32 + lane];
        acc.x += w * hv.x;
        acc.y += w * hv.y;
        den += w;
    }
    float inv = 1.f / (den + 1e-16f);
    float vx = acc.x * inv + b1[lane * 2];
    float vy = acc.y * inv + b1[lane * 2 + 1];
    vx = vx > 0.f ? vx : expm1f(vx);     // ELU
    vy = vy > 0.f ? vy : expm1f(vy);
    ((float2*)g_hact)[d * 32 + lane] = make_float2(vx, vy);
}

// ---------------- GEMM2: h2[N,40] = hact[N,64] @ W2[64,40] -------------------
__global__ void k_gemm2(const float* __restrict__ W2, int n) {
    __shared__ float Hs[64][65];
    __shared__ float Ws[64][NCLS];
    const int row0 = blockIdx.x * 64;
    const int t = threadIdx.x;

    for (int i = t; i < 64 * NCLS; i += 256) Ws[i / NCLS][i % NCLS] = W2[i];
#pragma unroll
    for (int i = 0; i < 16; i++) {
        int idx = t + i * 256;
        int r = idx >> 6, k = idx & 63;
        int row = row0 + r;
        Hs[r][k] = (row < n) ? g_hact[row * D1 + k] : 0.f;
    }
    __syncthreads();

    int r  = t >> 2;
    int c0 = (t & 3) * 10;
    float acc[10];
#pragma unroll
    for (int j = 0; j < 10; j++) acc[j] = 0.f;
#pragma unroll
    for (int k = 0; k < 64; k++) {
        float hv = Hs[r][k];
#pragma unroll
        for (int j = 0; j < 10; j++) acc[j] += hv * Ws[k][c0 + j];
    }
    int row = row0 + r;
    if (row < n)
#pragma unroll
        for (int j = 0; j < 10; j++) g_h2[row * NCLS + c0 + j] = acc[j];
}

// ---------------- layer-2 attention logits -----------------------------------
__global__ void k_node2a(const float* __restrict__ att_s, const float* __restrict__ att_d, int n) {
    int node = blockIdx.x * blockDim.x + threadIdx.x;
    if (node >= n) return;
    float a_s = 0.f, a_d = 0.f;
#pragma unroll
    for (int c = 0; c < NCLS; c++) {
        float hv = g_h2[node * NCLS + c];
        a_s += hv * att_s[c];
        a_d += hv * att_d[c];
    }
    g_as2[node] = a_s;
    g_ad2[node] = a_d;
}

// ---------------- layer-2 fused aggregate + softmax (warp per dst) ----------
__global__ void k_agg2(const float* __restrict__ b2, float* __restrict__ out, int n) {
    int warp = (blockIdx.x * blockDim.x + threadIdx.x) >> 5;
    int lane = threadIdx.x & 31;
    if (warp >= n) return;
    int d = warp;
    int c0 = lane, c1 = lane + 32;
    bool has1 = (c1 < NCLS);
    float adv = g_ad2[d];

    float acc0 = 0.f, acc1 = 0.f, den = 0.f;
    int s0 = g_row[d], s1 = g_row[d + 1];
#pragma unroll 4
    for (int j = s0; j < s1; j++) {
        int s = g_csr[j];
        float w = expf(lrelu(g_as2[s] + adv));
        acc0 += w * g_h2[s * NCLS + c0];
        if (has1) acc1 += w * g_h2[s * NCLS + c1];
        den += w;
    }
    // self loop
    {
        float w = expf(lrelu(g_as2[d] + adv));
        acc0 += w * g_h2[d * NCLS + c0];
        if (has1) acc1 += w * g_h2[d * NCLS + c1];
        den += w;
    }
    float inv = 1.f / (den + 1e-16f);
    float v0 = acc0 * inv + b2[c0];
    float v1 = has1 ? acc1 * inv + b2[c1] : -INFINITY;

    // warp softmax over 40 values
    float m = fmaxf(v0, v1);
#pragma unroll
    for (int o = 16; o > 0; o >>= 1) m = fmaxf(m, __shfl_xor_sync(0xFFFFFFFFu, m, o));
    float e0 = expf(v0 - m);
    float e1 = has1 ? expf(v1 - m) : 0.f;
    float ssum = e0 + e1;
#pragma unroll
    for (int o = 16; o > 0; o >>= 1) ssum += __shfl_xor_sync(0xFFFFFFFFu, ssum, o);
    float r = 1.f / ssum;
    out[d * NCLS + c0] = e0 * r;
    if (has1) out[d * NCLS + c1] = e1 * r;
}

// ---------------- launch ------------------------------------------------------
extern "C" void kernel_launch(void* const* d_in, const int* in_sizes, int n_in,
                              void* d_out, int out_size) {
    const float* x   = (const float*)d_in[0];
    const void*  ei  = d_in[1];
    const float* W1  = (const float*)d_in[2];
    const float* as1 = (const float*)d_in[3];
    const float* ad1 = (const float*)d_in[4];
    const float* b1  = (const float*)d_in[5];
    const float* W2  = (const float*)d_in[6];
    const float* as2 = (const float*)d_in[7];
    const float* ad2 = (const float*)d_in[8];
    const float* b2  = (const float*)d_in[9];
    float* out = (float*)d_out;

    int n = in_sizes[0] / FIN;       // 100000
    int E = in_sizes[1] / 2;         // 1600000
    int nb = (n + SCAN_B - 1) / SCAN_B;

    // CSR build
    k_detect <<<1, 32>>>((const int*)ei);
    k_zero   <<<(n + 255) / 256, 256>>>(n);
    k_build  <<<(E + 255) / 256, 256>>>(ei, E);
    k_scan1  <<<nb, SCAN_B>>>(n);
    k_scan2  <<<1, SCAN_B>>>(nb);
    k_scan3  <<<(n + 1 + 255) / 256, 256>>>(n, E);
    k_scatter<<<(E + 255) / 256, 256>>>(E);

    // layer 1
    k_gemm1  <<<(n + 63) / 64, 256>>>(x, W1, n);
    k_node1a <<<(n * H1 + 255) / 256, 256>>>(as1, ad1, n);
    k_agg1   <<<(n * 32 + 255) / 256, 256>>>(b1, n);

    // layer 2
    k_gemm2  <<<(n + 63) / 64, 256>>>(W2, n);
    k_node2a <<<(n + 255) / 256, 256>>>(as2, ad2, n);
    k_agg2   <<<(n * 32 + 255) / 256, 256>>>(b2, out, n);
}

// round 3
// speedup vs baseline: 1.8748x; 1.7394x over previous
#include <cuda_runtime.h>
#include <math.h>
#include <stdint.h>

#define NMAX  100000
#define EMAX  1600000
#define FIN   512
#define H1    8
#define D1    64      // H1 * C1
#define NCLS  40
#define SLOPE 0.2f
#define SCAN_B 1024

// ---------------- scratch (static device globals; no allocations) ----------
__device__ int g_is64;
__device__ __align__(256) int   g_src [EMAX];
__device__ __align__(256) int   g_dst [EMAX];
__device__ __align__(256) int   g_csr [EMAX];      // src ids grouped by dst
__device__ __align__(256) int   g_deg [NMAX];
__device__ __align__(256) int   g_row [NMAX + 1];  // CSR row pointers
__device__ __align__(256) int   g_cur [NMAX];
__device__ __align__(256) int   g_bsum[SCAN_B];
__device__ __align__(256) float g_h1  [NMAX * D1];
__device__ __align__(256) float g_as1 [NMAX * H1];
__device__ __align__(256) float g_ad1 [NMAX * H1];
__device__ __align__(256) float g_hact[NMAX * D1];
__device__ __align__(256) float g_h2  [NMAX * NCLS];
__device__ __align__(256) float g_as2 [NMAX];
__device__ __align__(256) float g_ad2 [NMAX];

__device__ __forceinline__ float lrelu(float v) { return v > 0.f ? v : SLOPE * v; }

__device__ __forceinline__ uint32_t f2tf32(float f) {
    uint32_t u;
    asm("cvt.rna.tf32.f32 %0, %1;" : "=r"(u) : "f"(f));
    return u;
}

// ---------------- edge index normalization + degree histogram ---------------
__global__ void k_detect(const int* __restrict__ ei) {
    if (threadIdx.x == 0 && blockIdx.x == 0) {
        int nz = 0;
        for (int i = 1; i < 64; i += 2) nz |= ei[i];   // int64 high words all zero?
        g_is64 = (nz == 0) ? 1 : 0;
    }
}

__global__ void k_zero(int n) {
    int i = blockIdx.x * blockDim.x + threadIdx.x;
    if (i < n) g_deg[i] = 0;
}

__global__ void k_build(const void* __restrict__ ei, int E) {
    int i = blockIdx.x * blockDim.x + threadIdx.x;
    if (i >= E) return;
    int s, d;
    if (g_is64) {
        const long long* p = (const long long*)ei;
        s = (int)p[i];
        d = (int)p[(long long)E + i];
    } else {
        const int* p = (const int*)ei;
        s = p[i];
        d = p[E + i];
    }
    g_src[i] = s;
    g_dst[i] = d;
    atomicAdd(&g_deg[d], 1);
}

// ---------------- exclusive scan of g_deg -> g_row --------------------------
__global__ void k_scan1(int n) {
    __shared__ int sh[SCAN_B];
    int tid = threadIdx.x;
    int i = blockIdx.x * SCAN_B + tid;
    int v = (i < n) ? g_deg[i] : 0;
    sh[tid] = v;
    __syncthreads();
#pragma unroll
    for (int off = 1; off < SCAN_B; off <<= 1) {
        int t = (tid >= off) ? sh[tid - off] : 0;
        __syncthreads();
        sh[tid] += t;
        __syncthreads();
    }
    if (i < n) g_row[i] = sh[tid] - v;          // local exclusive
    if (tid == SCAN_B - 1) g_bsum[blockIdx.x] = sh[tid];
}

__global__ void k_scan2(int nb) {
    __shared__ int sh[SCAN_B];
    int tid = threadIdx.x;
    int v = (tid < nb) ? g_bsum[tid] : 0;
    sh[tid] = v;
    __syncthreads();
#pragma unroll
    for (int off = 1; off < SCAN_B; off <<= 1) {
        int t = (tid >= off) ? sh[tid - off] : 0;
        __syncthreads();
        sh[tid] += t;
        __syncthreads();
    }
    g_bsum[tid] = sh[tid] - v;                  // exclusive block offsets
}

__global__ void k_scan3(int n, int E) {
    int i = blockIdx.x * blockDim.x + threadIdx.x;
    if (i < n) {
        int r = g_row[i] + g_bsum[i >> 10];
        g_row[i] = r;
        g_cur[i] = r;
    } else if (i == n) {
        g_row[n] = E;
    }
}

__global__ void k_scatter(int E) {
    int i = blockIdx.x * blockDim.x + threadIdx.x;
    if (i >= E) return;
    int d = g_dst[i];
    int pos = atomicAdd(&g_cur[d], 1);
    g_csr[pos] = g_src[i];
}

// ---------------- GEMM1 (TF32 tensor core): h1 = x @ W1 ---------------------
// block tile M=128 N=64 K=32; 8 warps 4x2; warp tile 32x32; mma m16n8k8
__global__ void k_gemm1(const float* __restrict__ x, const float* __restrict__ W, int n) {
    __shared__ float As[128][36];   // [m][k], bank = (4g + tg) -> conflict-free frag reads
    __shared__ float Bs[32][72];    // [k][n], bank = (8tg + g) -> conflict-free frag reads
    const int t    = threadIdx.x;
    const int warp = t >> 5, lane = t & 31;
    const int g    = lane >> 2, tg = lane & 3;
    const int wm   = warp >> 1, wn = warp & 1;
    const int m0   = wm * 32, n0 = wn * 32;
    const int row0 = blockIdx.x * 128;

    float c[2][4][4];
#pragma unroll
    for (int mi = 0; mi < 2; mi++)
#pragma unroll
        for (int nj = 0; nj < 4; nj++)
#pragma unroll
            for (int q = 0; q < 4; q++) c[mi][nj][q] = 0.f;

    for (int k0 = 0; k0 < FIN; k0 += 32) {
        // A: 128x32 floats = 1024 float4, 4 per thread
#pragma unroll
        for (int p = 0; p < 4; p++) {
            int idx = t + p * 256;
            int r = idx >> 3, c4 = idx & 7;
            float4 v = make_float4(0.f, 0.f, 0.f, 0.f);
            if (row0 + r < n)
                v = *(const float4*)(x + (size_t)(row0 + r) * FIN + k0 + c4 * 4);
            uint32_t* dstp = (uint32_t*)&As[r][c4 * 4];
            dstp[0] = f2tf32(v.x); dstp[1] = f2tf32(v.y);
            dstp[2] = f2tf32(v.z); dstp[3] = f2tf32(v.w);
        }
        // B: 32x64 floats = 512 float4, 2 per thread
#pragma unroll
        for (int p = 0; p < 2; p++) {
            int idx = t + p * 256;
            int kk = idx >> 4, n4 = idx & 15;
            float4 v = *(const float4*)(W + (size_t)(k0 + kk) * D1 + n4 * 4);
            uint32_t* dstp = (uint32_t*)&Bs[kk][n4 * 4];
            dstp[0] = f2tf32(v.x); dstp[1] = f2tf32(v.y);
            dstp[2] = f2tf32(v.z); dstp[3] = f2tf32(v.w);
        }
        __syncthreads();
#pragma unroll
        for (int ks = 0; ks < 4; ks++) {
            const int kb = ks * 8;
            uint32_t a[2][4], b[4][2];
#pragma unroll
            for (int mi = 0; mi < 2; mi++) {
                const int mr = m0 + mi * 16;
                a[mi][0] = __float_as_uint(As[mr + g    ][kb + tg    ]);
                a[mi][1] = __float_as_uint(As[mr + g + 8][kb + tg    ]);
                a[mi][2] = __float_as_uint(As[mr + g    ][kb + tg + 4]);
                a[mi][3] = __float_as_uint(As[mr + g + 8][kb + tg + 4]);
            }
#pragma unroll
            for (int nj = 0; nj < 4; nj++) {
                const int nc = n0 + nj * 8;
                b[nj][0] = __float_as_uint(Bs[kb + tg    ][nc + g]);
                b[nj][1] = __float_as_uint(Bs[kb + tg + 4][nc + g]);
            }
#pragma unroll
            for (int mi = 0; mi < 2; mi++)
#pragma unroll
                for (int nj = 0; nj < 4; nj++) {
                    asm volatile(
                        "mma.sync.aligned.m16n8k8.row.col.f32.tf32.tf32.f32 "
                        "{%0,%1,%2,%3}, {%4,%5,%6,%7}, {%8,%9}, {%0,%1,%2,%3};\n"
                        : "+f"(c[mi][nj][0]), "+f"(c[mi][nj][1]),
                          "+f"(c[mi][nj][2]), "+f"(c[mi][nj][3])
                        : "r"(a[mi][0]), "r"(a[mi][1]), "r"(a[mi][2]), "r"(a[mi][3]),
                          "r"(b[nj][0]), "r"(b[nj][1]));
                }
        }
        __syncthreads();
    }
    // epilogue
#pragma unroll
    for (int mi = 0; mi < 2; mi++) {
#pragma unroll
        for (int nj = 0; nj < 4; nj++) {
            int r1 = row0 + m0 + mi * 16 + g;
            int cc = n0 + nj * 8 + 2 * tg;
            if (r1 < n)
                *(float2*)(g_h1 + (size_t)r1 * D1 + cc) = make_float2(c[mi][nj][0], c[mi][nj][1]);
            if (r1 + 8 < n)
                *(float2*)(g_h1 + (size_t)(r1 + 8) * D1 + cc) = make_float2(c[mi][nj][2], c[mi][nj][3]);
        }
    }
}

// ---------------- layer-1 attention logits -----------------------------------
__global__ void k_node1a(const float* __restrict__ att_s, const float* __restrict__ att_d, int n) {
    int gid = blockIdx.x * blockDim.x + threadIdx.x;
    if (gid >= n * H1) return;
    int node = gid >> 3, h = gid & 7;
    int base = node * D1 + h * 8;
    float a_s = 0.f, a_d = 0.f;
#pragma unroll
    for (int c = 0; c < 8; c++) {
        float hv = g_h1[base + c];
        a_s += hv * att_s[h * 8 + c];
        a_d += hv * att_d[h * 8 + c];
    }
    g_as1[gid] = a_s;
    g_ad1[gid] = a_d;
}

// ---------------- layer-1 fused aggregate + epilogue (warp per dst) ---------
__global__ void k_agg1(const float* __restrict__ b1, int n) {
    int warp = (blockIdx.x * blockDim.x + threadIdx.x) >> 5;
    int lane = threadIdx.x & 31;
    if (warp >= n) return;
    int d = warp;
    int h = lane >> 2;
    float adv = g_ad1[d * 8 + h];

    float2 acc = make_float2(0.f, 0.f);
    float den = 0.f;

    int s0 = g_row[d], s1 = g_row[d + 1];
#pragma unroll 4
    for (int j = s0; j < s1; j++) {
        int s = g_csr[j];
        float a = g_as1[s * 8 + h];
        float w = __expf(lrelu(a + adv));
        float2 hv = ((const float2*)g_h1)[s * 32 + lane];
        acc.x += w * hv.x;
        acc.y += w * hv.y;
        den += w;
    }
    {
        float w = __expf(lrelu(g_as1[d * 8 + h] + adv));
        float2 hv = ((const float2*)g_h1)[d * 32 + lane];
        acc.x += w * hv.x;
        acc.y += w * hv.y;
        den += w;
    }
    float inv = 1.f / (den + 1e-16f);
    float vx = acc.x * inv + b1[lane * 2];
    float vy = acc.y * inv + b1[lane * 2 + 1];
    vx = vx > 0.f ? vx : expm1f(vx);
    vy = vy > 0.f ? vy : expm1f(vy);
    ((float2*)g_hact)[d * 32 + lane] = make_float2(vx, vy);
}

// ---------------- GEMM2: h2[N,40] = hact[N,64] @ W2[64,40] -------------------
__global__ void k_gemm2(const float* __restrict__ W2, int n) {
    __shared__ float Hs[64][65];
    __shared__ float Ws[64][NCLS];
    const int row0 = blockIdx.x * 64;
    const int t = threadIdx.x;

    for (int i = t; i < 64 * NCLS; i += 256) Ws[i / NCLS][i % NCLS] = W2[i];
#pragma unroll
    for (int i = 0; i < 16; i++) {
        int idx = t + i * 256;
        int r = idx >> 6, k = idx & 63;
        int row = row0 + r;
        Hs[r][k] = (row < n) ? g_hact[row * D1 + k] : 0.f;
    }
    __syncthreads();

    int r  = t >> 2;
    int c0 = (t & 3) * 10;
    float acc[10];
#pragma unroll
    for (int j = 0; j < 10; j++) acc[j] = 0.f;
#pragma unroll
    for (int k = 0; k < 64; k++) {
        float hv = Hs[r][k];
#pragma unroll
        for (int j = 0; j < 10; j++) acc[j] += hv * Ws[k][c0 + j];
    }
    int row = row0 + r;
    if (row < n)
#pragma unroll
        for (int j = 0; j < 10; j++) g_h2[row * NCLS + c0 + j] = acc[j];
}

// ---------------- layer-2 attention logits -----------------------------------
__global__ void k_node2a(const float* __restrict__ att_s, const float* __restrict__ att_d, int n) {
    int node = blockIdx.x * blockDim.x + threadIdx.x;
    if (node >= n) return;
    float a_s = 0.f, a_d = 0.f;
#pragma unroll
    for (int c = 0; c < NCLS; c++) {
        float hv = g_h2[node * NCLS + c];
        a_s += hv * att_s[c];
        a_d += hv * att_d[c];
    }
    g_as2[node] = a_s;
    g_ad2[node] = a_d;
}

// ---------------- layer-2 fused aggregate + softmax (warp per dst) ----------
__global__ void k_agg2(const float* __restrict__ b2, float* __restrict__ out, int n) {
    int warp = (blockIdx.x * blockDim.x + threadIdx.x) >> 5;
    int lane = threadIdx.x & 31;
    if (warp >= n) return;
    int d = warp;
    int c0 = lane, c1 = lane + 32;
    bool has1 = (c1 < NCLS);
    float adv = g_ad2[d];

    float acc0 = 0.f, acc1 = 0.f, den = 0.f;
    int s0 = g_row[d], s1 = g_row[d + 1];
#pragma unroll 4
    for (int j = s0; j < s1; j++) {
        int s = g_csr[j];
        float w = __expf(lrelu(g_as2[s] + adv));
        acc0 += w * g_h2[s * NCLS + c0];
        if (has1) acc1 += w * g_h2[s * NCLS + c1];
        den += w;
    }
    {
        float w = __expf(lrelu(g_as2[d] + adv));
        acc0 += w * g_h2[d * NCLS + c0];
        if (has1) acc1 += w * g_h2[d * NCLS + c1];
        den += w;
    }
    float inv = 1.f / (den + 1e-16f);
    float v0 = acc0 * inv + b2[c0];
    float v1 = has1 ? acc1 * inv + b2[c1] : -INFINITY;

    float m = fmaxf(v0, v1);
#pragma unroll
    for (int o = 16; o > 0; o >>= 1) m = fmaxf(m, __shfl_xor_sync(0xFFFFFFFFu, m, o));
    float e0 = expf(v0 - m);
    float e1 = has1 ? expf(v1 - m) : 0.f;
    float ssum = e0 + e1;
#pragma unroll
    for (int o = 16; o > 0; o >>= 1) ssum += __shfl_xor_sync(0xFFFFFFFFu, ssum, o);
    float r = 1.f / ssum;
    out[d * NCLS + c0] = e0 * r;
    if (has1) out[d * NCLS + c1] = e1 * r;
}

// ---------------- launch ------------------------------------------------------
extern "C" void kernel_launch(void* const* d_in, const int* in_sizes, int n_in,
                              void* d_out, int out_size) {
    const float* x   = (const float*)d_in[0];
    const void*  ei  = d_in[1];
    const float* W1  = (const float*)d_in[2];
    const float* as1 = (const float*)d_in[3];
    const float* ad1 = (const float*)d_in[4];
    const float* b1  = (const float*)d_in[5];
    const float* W2  = (const float*)d_in[6];
    const float* as2 = (const float*)d_in[7];
    const float* ad2 = (const float*)d_in[8];
    const float* b2  = (const float*)d_in[9];
    float* out = (float*)d_out;

    int n = in_sizes[0] / FIN;       // 100000
    int E = in_sizes[1] / 2;         // 1600000
    int nb = (n + SCAN_B - 1) / SCAN_B;

    // CSR build
    k_detect <<<1, 32>>>((const int*)ei);
    k_zero   <<<(n + 255) / 256, 256>>>(n);
    k_build  <<<(E + 255) / 256, 256>>>(ei, E);
    k_scan1  <<<nb, SCAN_B>>>(n);
    k_scan2  <<<1, SCAN_B>>>(nb);
    k_scan3  <<<(n + 1 + 255) / 256, 256>>>(n, E);
    k_scatter<<<(E + 255) / 256, 256>>>(E);

    // layer 1
    k_gemm1  <<<(n + 127) / 128, 256>>>(x, W1, n);
    k_node1a <<<(n * H1 + 255) / 256, 256>>>(as1, ad1, n);
    k_agg1   <<<(n * 32 + 255) / 256, 256>>>(b1, n);

    // layer 2
    k_gemm2  <<<(n + 63) / 64, 256>>>(W2, n);
    k_node2a <<<(n + 255) / 256, 256>>>(as2, ad2, n);
    k_agg2   <<<(n * 32 + 255) / 256, 256>>>(b2, out, n);
}

// round 5
// speedup vs baseline: 2.3035x; 1.2286x over previous
#include <cuda_runtime.h>
#include <cuda_fp16.h>
#include <math.h>
#include <stdint.h>

#define NMAX  100000
#define EMAX  1600000
#define FIN   512
#define H1    8
#define D1    64      // H1 * C1
#define NCLS  40
#define SLOPE 0.2f
#define SCAN_B 1024

// dynamic smem for k_gemm1: As[2][128][36] then Bs[2][32][72]
#define GEMM1_SMEM_FLOATS (2*128*36 + 2*32*72)   // 13824 floats = 55296 B
#define AS_OFF 0
#define BS_OFF (2*128*36)

// ---------------- scratch (static device globals; no allocations) ----------
__device__ int g_is64;
__device__ __align__(256) int    g_src [EMAX];
__device__ __align__(256) int    g_dst [EMAX];
__device__ __align__(256) int    g_csr [EMAX];      // src ids grouped by dst
__device__ __align__(256) int    g_deg [NMAX];
__device__ __align__(256) int    g_row [NMAX + 1];  // CSR row pointers
__device__ __align__(256) int    g_cur [NMAX];
__device__ __align__(256) int    g_bsum[SCAN_B];
__device__ __align__(256) __half g_h1h [NMAX * D1];    // h1 in fp16 (gathered)
__device__ __align__(256) float  g_as1 [NMAX * H1];
__device__ __align__(256) float  g_ad1 [NMAX * H1];
__device__ __align__(256) float  g_hact[NMAX * D1];
__device__ __align__(256) __half g_h2h [NMAX * NCLS];  // h2 in fp16 (gathered)
__device__ __align__(256) float  g_as2 [NMAX];
__device__ __align__(256) float  g_ad2 [NMAX];

__device__ __forceinline__ float lrelu(float v) { return v > 0.f ? v : SLOPE * v; }

// ---------------- zero degrees + detect int64 vs int32 ----------------------
__global__ void k_zero_detect(const int* __restrict__ ei, int n) {
    int i = blockIdx.x * blockDim.x + threadIdx.x;
    if (i < n) g_deg[i] = 0;
    if (i == 0) {
        int nz = 0;
        for (int k = 1; k < 64; k += 2) nz |= ei[k];   // int64 high words all zero?
        g_is64 = (nz == 0) ? 1 : 0;
    }
}

__global__ void k_build(const void* __restrict__ ei, int E) {
    int i = blockIdx.x * blockDim.x + threadIdx.x;
    if (i >= E) return;
    int s, d;
    if (g_is64) {
        const long long* p = (const long long*)ei;
        s = (int)p[i];
        d = (int)p[(long long)E + i];
    } else {
        const int* p = (const int*)ei;
        s = p[i];
        d = p[E + i];
    }
    g_src[i] = s;
    g_dst[i] = d;
    atomicAdd(&g_deg[d], 1);
}

// ---------------- exclusive scan of g_deg -> g_row --------------------------
__global__ void k_scan1(int n) {
    __shared__ int sh[SCAN_B];
    int tid = threadIdx.x;
    int i = blockIdx.x * SCAN_B + tid;
    int v = (i < n) ? g_deg[i] : 0;
    sh[tid] = v;
    __syncthreads();
#pragma unroll
    for (int off = 1; off < SCAN_B; off <<= 1) {
        int t = (tid >= off) ? sh[tid - off] : 0;
        __syncthreads();
        sh[tid] += t;
        __syncthreads();
    }
    if (i < n) g_row[i] = sh[tid] - v;
    if (tid == SCAN_B - 1) g_bsum[blockIdx.x] = sh[tid];
}

__global__ void k_scan2(int nb) {
    __shared__ int sh[SCAN_B];
    int tid = threadIdx.x;
    int v = (tid < nb) ? g_bsum[tid] : 0;
    sh[tid] = v;
    __syncthreads();
#pragma unroll
    for (int off = 1; off < SCAN_B; off <<= 1) {
        int t = (tid >= off) ? sh[tid - off] : 0;
        __syncthreads();
        sh[tid] += t;
        __syncthreads();
    }
    g_bsum[tid] = sh[tid] - v;
}

__global__ void k_scan3(int n, int E) {
    int i = blockIdx.x * blockDim.x + threadIdx.x;
    if (i < n) {
        int r = g_row[i] + g_bsum[i >> 10];
        g_row[i] = r;
        g_cur[i] = r;
    } else if (i == n) {
        g_row[n] = E;
    }
}

__global__ void k_scatter(int E) {
    int i = blockIdx.x * blockDim.x + threadIdx.x;
    if (i >= E) return;
    int d = g_dst[i];
    int pos = atomicAdd(&g_cur[d], 1);
    g_csr[pos] = g_src[i];
}

// ---------------- GEMM1 (TF32, cp.async double buffer) + fused logits -------
// block tile M=128 N=64 K=32; 8 warps 4x2; warp tile 32x32; mma m16n8k8
// dynamic smem: As stride 36 (bank 4g+tg), Bs stride 72 (bank 8tg+g) — conflict-free
__global__ void k_gemm1(const float* __restrict__ x, const float* __restrict__ W,
                        const float* __restrict__ attS, const float* __restrict__ attD, int n) {
    extern __shared__ float sm[];
    float* Asm = sm + AS_OFF;                       // [buf][128][36]
    float* Bsm = sm + BS_OFF;                       // [buf][32][72]
    const int t    = threadIdx.x;
    const int warp = t >> 5, lane = t & 31;
    const int g    = lane >> 2, tg = lane & 3;
    const int wm   = warp >> 1, wn = warp & 1;
    const int m0   = wm * 32, n0 = wn * 32;
    const int row0 = blockIdx.x * 128;

    float c[2][4][4];
#pragma unroll
    for (int mi = 0; mi < 2; mi++)
#pragma unroll
        for (int nj = 0; nj < 4; nj++)
#pragma unroll
            for (int q = 0; q < 4; q++) c[mi][nj][q] = 0.f;

    auto load_stage = [&](int stage, int buf) {
        const int k0 = stage * 32;
        float* Ab = Asm + buf * 128 * 36;
        float* Bb = Bsm + buf * 32 * 72;
#pragma unroll
        for (int p = 0; p < 4; p++) {              // A: 128x32 = 1024 float4
            int idx = t + p * 256;
            int r = idx >> 3, c4 = idx & 7;
            const float* src = x + (size_t)(row0 + r) * FIN + k0 + c4 * 4;
            uint32_t daddr = (uint32_t)__cvta_generic_to_shared(Ab + r * 36 + c4 * 4);
            int sb = (row0 + r < n) ? 16 : 0;
            asm volatile("cp.async.cg.shared.global [%0], [%1], 16, %2;\n"
                         :: "r"(daddr), "l"(src), "r"(sb));
        }
#pragma unroll
        for (int p = 0; p < 2; p++) {              // B: 32x64 = 512 float4
            int idx = t + p * 256;
            int kk = idx >> 4, n4 = idx & 15;
            const float* src = W + (size_t)(k0 + kk) * D1 + n4 * 4;
            uint32_t daddr = (uint32_t)__cvta_generic_to_shared(Bb + kk * 72 + n4 * 4);
            asm volatile("cp.async.cg.shared.global [%0], [%1], 16;\n"
                         :: "r"(daddr), "l"(src));
        }
    };

    load_stage(0, 0);
    asm volatile("cp.async.commit_group;\n");

    const int NSTAGE = FIN / 32;   // 16
    for (int it = 0; it < NSTAGE; it++) {
        if (it + 1 < NSTAGE) {
            load_stage(it + 1, (it + 1) & 1);
            asm volatile("cp.async.commit_group;\n");
            asm volatile("cp.async.wait_group 1;\n");
        } else {
            asm volatile("cp.async.wait_group 0;\n");
        }
        __syncthreads();
        const int buf = it & 1;
        const float* Ab = Asm + buf * 128 * 36;
        const float* Bb = Bsm + buf * 32 * 72;
#pragma unroll
        for (int ks = 0; ks < 4; ks++) {
            const int kb = ks * 8;
            uint32_t a[2][4], b[4][2];
#pragma unroll
            for (int mi = 0; mi < 2; mi++) {
                const int mr = m0 + mi * 16;
                a[mi][0] = __float_as_uint(Ab[(mr + g    ) * 36 + kb + tg    ]);
                a[mi][1] = __float_as_uint(Ab[(mr + g + 8) * 36 + kb + tg    ]);
                a[mi][2] = __float_as_uint(Ab[(mr + g    ) * 36 + kb + tg + 4]);
                a[mi][3] = __float_as_uint(Ab[(mr + g + 8) * 36 + kb + tg + 4]);
            }
#pragma unroll
            for (int nj = 0; nj < 4; nj++) {
                const int nc = n0 + nj * 8;
                b[nj][0] = __float_as_uint(Bb[(kb + tg    ) * 72 + nc + g]);
                b[nj][1] = __float_as_uint(Bb[(kb + tg + 4) * 72 + nc + g]);
            }
#pragma unroll
            for (int mi = 0; mi < 2; mi++)
#pragma unroll
                for (int nj = 0; nj < 4; nj++) {
                    asm volatile(
                        "mma.sync.aligned.m16n8k8.row.col.f32.tf32.tf32.f32 "
                        "{%0,%1,%2,%3}, {%4,%5,%6,%7}, {%8,%9}, {%0,%1,%2,%3};\n"
                        : "+f"(c[mi][nj][0]), "+f"(c[mi][nj][1]),
                          "+f"(c[mi][nj][2]), "+f"(c[mi][nj][3])
                        : "r"(a[mi][0]), "r"(a[mi][1]), "r"(a[mi][2]), "r"(a[mi][3]),
                          "r"(b[nj][0]), "r"(b[nj][1]));
                }
        }
        __syncthreads();
    }

    // ---- epilogue: fp16 h1 store + fused attention logits ----
#pragma unroll
    for (int mi = 0; mi < 2; mi++) {
        int r1 = row0 + m0 + mi * 16 + g;
        int r2 = r1 + 8;
#pragma unroll
        for (int nj = 0; nj < 4; nj++) {
            int hh = wn * 4 + nj;                 // head handled by this chunk
            float w0 = attS[hh * 8 + 2 * tg], w1 = attS[hh * 8 + 2 * tg + 1];
            float u0 = attD[hh * 8 + 2 * tg], u1 = attD[hh * 8 + 2 * tg + 1];
            float s1 = c[mi][nj][0] * w0 + c[mi][nj][1] * w1;
            float d1v = c[mi][nj][0] * u0 + c[mi][nj][1] * u1;
            float s2 = c[mi][nj][2] * w0 + c[mi][nj][3] * w1;
            float d2v = c[mi][nj][2] * u0 + c[mi][nj][3] * u1;
#pragma unroll
            for (int o = 1; o <= 2; o <<= 1) {
                s1  += __shfl_xor_sync(0xFFFFFFFFu, s1,  o);
                d1v += __shfl_xor_sync(0xFFFFFFFFu, d1v, o);
                s2  += __shfl_xor_sync(0xFFFFFFFFu, s2,  o);
                d2v += __shfl_xor_sync(0xFFFFFFFFu, d2v, o);
            }
            int cp = (n0 + nj * 8) / 2 + tg;      // half2 column index
            if (r1 < n) {
                ((__half2*)g_h1h)[r1 * 32 + cp] = __floats2half2_rn(c[mi][nj][0], c[mi][nj][1]);
                if (tg == 0) { g_as1[r1 * 8 + hh] = s1; g_ad1[r1 * 8 + hh] = d1v; }
            }
            if (r2 < n) {
                ((__half2*)g_h1h)[r2 * 32 + cp] = __floats2half2_rn(c[mi][nj][2], c[mi][nj][3]);
                if (tg == 0) { g_as1[r2 * 8 + hh] = s2; g_ad1[r2 * 8 + hh] = d2v; }
            }
        }
    }
}

// ---------------- layer-1 fused aggregate + epilogue (warp per dst) ---------
__global__ void k_agg1(const float* __restrict__ b1, int n) {
    int warp = (blockIdx.x * blockDim.x + threadIdx.x) >> 5;
    int lane = threadIdx.x & 31;
    if (warp >= n) return;
    int d = warp;
    int h = lane >> 2;                    // lane owns channels 2*lane, 2*lane+1
    float adv = g_ad1[d * 8 + h];

    float accx = 0.f, accy = 0.f, den = 0.f;
    int s0 = g_row[d], s1 = g_row[d + 1];
#pragma unroll 4
    for (int j = s0; j < s1; j++) {
        int s = g_csr[j];
        float w = __expf(lrelu(g_as1[s * 8 + h] + adv));
        float2 hv = __half22float2(((const __half2*)g_h1h)[s * 32 + lane]);
        accx += w * hv.x;
        accy += w * hv.y;
        den += w;
    }
    {   // self loop
        float w = __expf(lrelu(g_as1[d * 8 + h] + adv));
        float2 hv = __half22float2(((const __half2*)g_h1h)[d * 32 + lane]);
        accx += w * hv.x;
        accy += w * hv.y;
        den += w;
    }
    float inv = 1.f / (den + 1e-16f);
    float vx = accx * inv + b1[lane * 2];
    float vy = accy * inv + b1[lane * 2 + 1];
    vx = vx > 0.f ? vx : expm1f(vx);      // ELU
    vy = vy > 0.f ? vy : expm1f(vy);
    ((float2*)g_hact)[d * 32 + lane] = make_float2(vx, vy);
}

// ---------------- GEMM2 + fused layer-2 logits -------------------------------
__global__ void k_gemm2(const float* __restrict__ W2,
                        const float* __restrict__ attS, const float* __restrict__ attD, int n) {
    __shared__ float Hs[64][65];
    __shared__ float Ws[64][NCLS];
    const int row0 = blockIdx.x * 64;
    const int t = threadIdx.x;

    for (int i = t; i < 64 * NCLS; i += 256) Ws[i / NCLS][i % NCLS] = W2[i];
#pragma unroll
    for (int i = 0; i < 16; i++) {
        int idx = t + i * 256;
        int r = idx >> 6, k = idx & 63;
        int row = row0 + r;
        Hs[r][k] = (row < n) ? g_hact[row * D1 + k] : 0.f;
    }
    __syncthreads();

    int r  = t >> 2;
    int c0 = (t & 3) * 10;
    float acc[10];
#pragma unroll
    for (int j = 0; j < 10; j++) acc[j] = 0.f;
#pragma unroll
    for (int k = 0; k < 64; k++) {
        float hv = Hs[r][k];
#pragma unroll
        for (int j = 0; j < 10; j++) acc[j] += hv * Ws[k][c0 + j];
    }

    // fused logits: reduce over the 4 threads covering this row
    float asp = 0.f, adp = 0.f;
#pragma unroll
    for (int j = 0; j < 10; j++) {
        asp += acc[j] * attS[c0 + j];
        adp += acc[j] * attD[c0 + j];
    }
#pragma unroll
    for (int o = 1; o <= 2; o <<= 1) {
        asp += __shfl_xor_sync(0xFFFFFFFFu, asp, o);
        adp += __shfl_xor_sync(0xFFFFFFFFu, adp, o);
    }

    int row = row0 + r;
    if (row < n) {
#pragma unroll
        for (int j = 0; j < 10; j += 2)
            ((__half2*)g_h2h)[row * 20 + (c0 + j) / 2] = __floats2half2_rn(acc[j], acc[j + 1]);
        if ((t & 3) == 0) { g_as2[row] = asp; g_ad2[row] = adp; }
    }
}

// ---------------- layer-2 fused aggregate + softmax (warp per dst) ----------
__global__ void k_agg2(const float* __restrict__ b2, float* __restrict__ out, int n) {
    int warp = (blockIdx.x * blockDim.x + threadIdx.x) >> 5;
    int lane = threadIdx.x & 31;
    if (warp >= n) return;
    int d = warp;
    bool act = lane < 20;                 // lane owns channels 2*lane, 2*lane+1
    float adv = g_ad2[d];

    float acc0 = 0.f, acc1 = 0.f, den = 0.f;
    int s0 = g_row[d], s1 = g_row[d + 1];
#pragma unroll 4
    for (int j = s0; j < s1; j++) {
        int s = g_csr[j];
        float w = __expf(lrelu(g_as2[s] + adv));
        den += w;
        if (act) {
            float2 hv = __half22float2(((const __half2*)g_h2h)[s * 20 + lane]);
            acc0 += w * hv.x;
            acc1 += w * hv.y;
        }
    }
    {   // self loop
        float w = __expf(lrelu(g_as2[d] + adv));
        den += w;
        if (act) {
            float2 hv = __half22float2(((const __half2*)g_h2h)[d * 20 + lane]);
            acc0 += w * hv.x;
            acc1 += w * hv.y;
        }
    }
    float inv = 1.f / (den + 1e-16f);
    float v0 = act ? acc0 * inv + b2[2 * lane]     : -INFINITY;
    float v1 = act ? acc1 * inv + b2[2 * lane + 1] : -INFINITY;

    float m = fmaxf(v0, v1);
#pragma unroll
    for (int o = 16; o > 0; o >>= 1) m = fmaxf(m, __shfl_xor_sync(0xFFFFFFFFu, m, o));
    float e0 = act ? expf(v0 - m) : 0.f;
    float e1 = act ? expf(v1 - m) : 0.f;
    float ssum = e0 + e1;
#pragma unroll
    for (int o = 16; o > 0; o >>= 1) ssum += __shfl_xor_sync(0xFFFFFFFFu, ssum, o);
    float rr = 1.f / ssum;
    if (act) ((float2*)(out + (size_t)d * NCLS))[lane] = make_float2(e0 * rr, e1 * rr);
}

// ---------------- launch ------------------------------------------------------
extern "C" void kernel_launch(void* const* d_in, const int* in_sizes, int n_in,
                              void* d_out, int out_size) {
    const float* x    = (const float*)d_in[0];
    const void*  ei   = d_in[1];
    const float* W1   = (const float*)d_in[2];
    const float* as1w = (const float*)d_in[3];
    const float* ad1w = (const float*)d_in[4];
    const float* b1   = (const float*)d_in[5];
    const float* W2   = (const float*)d_in[6];
    const float* as2w = (const float*)d_in[7];
    const float* ad2w = (const float*)d_in[8];
    const float* b2   = (const float*)d_in[9];
    float* out = (float*)d_out;

    int n = in_sizes[0] / FIN;       // 100000
    int E = in_sizes[1] / 2;         // 1600000
    int nb = (n + SCAN_B - 1) / SCAN_B;

    const int gemm1_smem = GEMM1_SMEM_FLOATS * 4;   // 55296 bytes
    cudaFuncSetAttribute(k_gemm1, cudaFuncAttributeMaxDynamicSharedMemorySize, gemm1_smem);

    // CSR build
    k_zero_detect<<<(n + 255) / 256, 256>>>((const int*)ei, n);
    k_build  <<<(E + 255) / 256, 256>>>(ei, E);
    k_scan1  <<<nb, SCAN_B>>>(n);
    k_scan2  <<<1, SCAN_B>>>(nb);
    k_scan3  <<<(n + 1 + 255) / 256, 256>>>(n, E);
    k_scatter<<<(E + 255) / 256, 256>>>(E);

    // layer 1
    k_gemm1  <<<(n + 127) / 128, 256, gemm1_smem>>>(x, W1, as1w, ad1w, n);
    k_agg1   <<<(n * 32 + 255) / 256, 256>>>(b1, n);

    // layer 2
    k_gemm2  <<<(n + 63) / 64, 256>>>(W2, as2w, ad2w, n);
    k_agg2   <<<(n * 32 + 255) / 256, 256>>>(b2, out, n);
}